// round 2
// baseline (speedup 1.0000x reference)
#include <cuda_runtime.h>
#include <math.h>

#define Bn 64
#define Tn 512
#define En 768
#define Cn 20
#define FULL 0xffffffffu

// scratch (no allocations allowed)
__device__ float g_em[Bn * Tn * Cn];   // emissions [B][T][C]
__device__ float g_norm[Bn];
__device__ float g_score[Bn];

__device__ __forceinline__ float neg_inf() { return __int_as_float(0xff800000); }

// ---------------------------------------------------------------------------
// Kernel 1: emissions = hidden @ fc_w^T + fc_b      (warp per row)
// ---------------------------------------------------------------------------
extern "C" __global__ void k_emissions(const float* __restrict__ hidden,
                                       const float* __restrict__ fc_w,
                                       const float* __restrict__ fc_b) {
    extern __shared__ float sm[];          // Cn*En weights + Cn bias
    float* wsh = sm;
    float* bsh = sm + Cn * En;
    for (int i = threadIdx.x; i < Cn * En; i += blockDim.x) wsh[i] = fc_w[i];
    if (threadIdx.x < Cn) bsh[threadIdx.x] = fc_b[threadIdx.x];
    __syncthreads();

    const int lane  = threadIdx.x & 31;
    const int warp  = threadIdx.x >> 5;
    const int nwarp = (blockDim.x >> 5) * gridDim.x;
    const float4* w4 = (const float4*)wsh;

    for (int row = blockIdx.x * (blockDim.x >> 5) + warp; row < Bn * Tn; row += nwarp) {
        const float4* h4 = (const float4*)(hidden + (size_t)row * En);
        float acc[Cn];
#pragma unroll
        for (int c = 0; c < Cn; c++) acc[c] = (lane == 0) ? bsh[c] : 0.f;

#pragma unroll
        for (int k = 0; k < En / 128; k++) {           // 6 chunks of 128 floats
            float4 h = h4[lane + 32 * k];
#pragma unroll
            for (int c = 0; c < Cn; c++) {
                float4 w = w4[c * (En / 4) + lane + 32 * k];
                acc[c] = fmaf(h.x, w.x, fmaf(h.y, w.y, fmaf(h.z, w.z, fmaf(h.w, w.w, acc[c]))));
            }
        }
#pragma unroll
        for (int c = 0; c < Cn; c++) {
            acc[c] += __shfl_xor_sync(FULL, acc[c], 16);
            acc[c] += __shfl_xor_sync(FULL, acc[c], 8);
            acc[c] += __shfl_xor_sync(FULL, acc[c], 4);
            acc[c] += __shfl_xor_sync(FULL, acc[c], 2);
            acc[c] += __shfl_xor_sync(FULL, acc[c], 1);
        }
        if (lane == 0) {
            float4* o4 = (float4*)(g_em + (size_t)row * Cn);   // 80B stride: 16B aligned
            o4[0] = make_float4(acc[0],  acc[1],  acc[2],  acc[3]);
            o4[1] = make_float4(acc[4],  acc[5],  acc[6],  acc[7]);
            o4[2] = make_float4(acc[8],  acc[9],  acc[10], acc[11]);
            o4[3] = make_float4(acc[12], acc[13], acc[14], acc[15]);
            o4[4] = make_float4(acc[16], acc[17], acc[18], acc[19]);
        }
    }
}

// ---------------------------------------------------------------------------
// Kernel 2: blocks 0..63  -> numerator score + scaled forward (per batch)
//           blocks 64..127-> viterbi + backtrace, writes path into dout[1..]
// one warp (32 threads) per block; emissions staged into smem
// ---------------------------------------------------------------------------
#define SM_EM    (Tn * Cn * 4)                 // 40960
#define SM_MSK   (Tn * 4)                      // 2048
#define SM_HIST  ((Tn - 1) * Cn)               // 10220
#define SM2_SIZE (SM_EM + SM_MSK + SM_HIST + 16)

extern "C" __global__ void k_crf(const int* __restrict__ amask,
                                 const int* __restrict__ labels,
                                 const float* __restrict__ start_t,
                                 const float* __restrict__ end_t,
                                 const float* __restrict__ trans,
                                 float* __restrict__ dout) {
    extern __shared__ char smraw[];
    float*         em_sh = (float*)smraw;
    int*           msk   = (int*)(smraw + SM_EM);
    unsigned char* hist  = (unsigned char*)(smraw + SM_EM + SM_MSK);

    const int lane = threadIdx.x;
    const bool isfwd = (blockIdx.x < Bn);
    const int b = isfwd ? blockIdx.x : blockIdx.x - Bn;
    const bool act = lane < Cn;
    const int jj = act ? lane : 0;          // clamped state index (avoid OOB)

    // stage emissions + mask for this batch
    {
        const float4* src = (const float4*)(g_em + (size_t)b * Tn * Cn);
        float4* dst = (float4*)em_sh;
        for (int i = lane; i < Tn * Cn / 4; i += 32) dst[i] = src[i];
        for (int i = lane; i < Tn; i += 32) msk[i] = amask[b * Tn + i];
    }
    __syncwarp();

    if (isfwd) {
        // ---- numerator: gold path score ----
        float ns = 0.f; int msum = 0;
        for (int t = lane; t < Tn; t += 32) {
            int tg = labels[b * Tn + t];
            msum += msk[t];
            if (t == 0) {
                ns += start_t[tg] + em_sh[tg];
            } else if (msk[t]) {
                int tp = labels[b * Tn + t - 1];
                ns += trans[tp * Cn + tg] + em_sh[t * Cn + tg];
            }
        }
        for (int o = 16; o; o >>= 1) {
            ns   += __shfl_xor_sync(FULL, ns, o);
            msum += __shfl_xor_sync(FULL, msum, o);
        }
        if (lane == 0) {
            int se = msum - 1;
            g_score[b] = ns + end_t[labels[b * Tn + se]];
        }

        // ---- denominator: scaled linear-domain forward ----
        float Mc[Cn];
#pragma unroll
        for (int i = 0; i < Cn; i++) Mc[i] = act ? expf(trans[i * Cn + jj]) : 0.f;

        float p = act ? expf(start_t[jj] + em_sh[jj]) : 0.f;
        float logZ = 0.f;

        for (int t = 1; t < Tn; t++) {
            float Ev = __expf(em_sh[t * Cn + jj]);    // off critical path
            float q0 = 0.f, q1 = 0.f, q2 = 0.f, q3 = 0.f;
#pragma unroll
            for (int i = 0; i < Cn; i += 4) {
                q0 = fmaf(__shfl_sync(FULL, p, i + 0), Mc[i + 0], q0);
                q1 = fmaf(__shfl_sync(FULL, p, i + 1), Mc[i + 1], q1);
                q2 = fmaf(__shfl_sync(FULL, p, i + 2), Mc[i + 2], q2);
                q3 = fmaf(__shfl_sync(FULL, p, i + 3), Mc[i + 3], q3);
            }
            float r = ((q0 + q1) + (q2 + q3)) * Ev;
            p = (msk[t] > 0) ? r : p;                 // lanes>=20 stay 0
            if ((t & 7) == 0) {                       // renormalize every 8 steps
                float s = p;
                for (int o = 16; o; o >>= 1) s += __shfl_xor_sync(FULL, s, o);
                p *= __fdividef(1.f, s);
                logZ += __logf(s);
            }
        }
        float fin = act ? p * __expf(end_t[jj]) : 0.f;
        for (int o = 16; o; o >>= 1) fin += __shfl_xor_sync(FULL, fin, o);
        if (lane == 0) g_norm[b] = logZ + __logf(fin);

    } else {
        // ---- viterbi (bitwise-exact max recurrence, first-argmax ties) ----
        float Tc[Cn];
#pragma unroll
        for (int i = 0; i < Cn; i++) Tc[i] = act ? trans[i * Cn + jj] : 0.f;

        float a = act ? (start_t[jj] + em_sh[jj]) : neg_inf();

        for (int t = 1; t < Tn; t++) {
            float v[Cn];
#pragma unroll
            for (int i = 0; i < Cn; i++) v[i] = __shfl_sync(FULL, a, i) + Tc[i];

            // ordered tournament: strictly-greater takes right => first max wins
            float w[10]; int wi[10];
#pragma unroll
            for (int k = 0; k < 10; k++) {
                bool tk = v[2 * k + 1] > v[2 * k];
                w[k] = tk ? v[2 * k + 1] : v[2 * k];
                wi[k] = tk ? 2 * k + 1 : 2 * k;
            }
            float x[5]; int xi[5];
#pragma unroll
            for (int k = 0; k < 5; k++) {
                bool tk = w[2 * k + 1] > w[2 * k];
                x[k] = tk ? w[2 * k + 1] : w[2 * k];
                xi[k] = tk ? wi[2 * k + 1] : wi[2 * k];
            }
            bool t0 = x[1] > x[0];
            float y0 = t0 ? x[1] : x[0]; int y0i = t0 ? xi[1] : xi[0];
            bool t1 = x[3] > x[2];
            float y1 = t1 ? x[3] : x[2]; int y1i = t1 ? xi[3] : xi[2];
            bool t2 = y1 > y0;
            float z  = t2 ? y1 : y0;     int zi  = t2 ? y1i : y0i;
            bool t3 = x[4] > z;
            float best = t3 ? x[4] : z;  int bi  = t3 ? xi[4] : zi;

            if (act) hist[(t - 1) * Cn + lane] = (unsigned char)bi;

            float na = best + em_sh[t * Cn + jj];
            a = (msk[t] > 0) ? na : a;    // garbage on inactive lanes, never read
        }

        // final argmax over states (first max on ties)
        float fv = act ? a + end_t[jj] : neg_inf();
        int fi = lane;
        for (int o = 16; o; o >>= 1) {
            float ov = __shfl_xor_sync(FULL, fv, o);
            int   oi = __shfl_xor_sync(FULL, fi, o);
            bool tk = (ov > fv) || (ov == fv && oi < fi);
            fv = tk ? ov : fv;
            fi = tk ? oi : fi;
        }
        __syncwarp();
        if (lane == 0) {
            int tg = fi;
            dout[1 + b * Tn + (Tn - 1)] = (float)(tg + 1);
            for (int t = Tn - 2; t >= 0; t--) {
                tg = hist[t * Cn + tg];
                dout[1 + b * Tn + t] = (float)(tg + 1);
            }
        }
    }
}

// ---------------------------------------------------------------------------
// Kernel 3: loss = mean(norm - score)   (one warp, serial-safe)
// ---------------------------------------------------------------------------
extern "C" __global__ void k_loss(float* __restrict__ dout) {
    int i = threadIdx.x;                          // 32 threads
    float v = g_norm[i] - g_score[i];
    v += g_norm[i + 32] - g_score[i + 32];
    for (int o = 16; o; o >>= 1) v += __shfl_xor_sync(FULL, v, o);
    if (i == 0) dout[0] = v / (float)Bn;
}

// ---------------------------------------------------------------------------
extern "C" void kernel_launch(void* const* d_in, const int* in_sizes, int n_in,
                              void* d_out, int out_size) {
    const float* hidden = (const float*)d_in[0];
    const int*   amask  = (const int*)d_in[1];
    const int*   labels = (const int*)d_in[2];
    const float* fc_w   = (const float*)d_in[3];
    const float* fc_b   = (const float*)d_in[4];
    const float* st     = (const float*)d_in[5];
    const float* en     = (const float*)d_in[6];
    const float* tr     = (const float*)d_in[7];
    float* dout = (float*)d_out;

    const int smem1 = (Cn * En + Cn) * 4;
    (void)cudaFuncSetAttribute((const void*)k_emissions,
                               cudaFuncAttributeMaxDynamicSharedMemorySize, smem1);
    (void)cudaFuncSetAttribute((const void*)k_crf,
                               cudaFuncAttributeMaxDynamicSharedMemorySize, SM2_SIZE);

    k_emissions<<<148, 256, smem1>>>(hidden, fc_w, fc_b);
    k_crf<<<2 * Bn, 32, SM2_SIZE>>>(amask, labels, st, en, tr, dout);
    k_loss<<<1, 32>>>(dout);
}

// round 3
// speedup vs baseline: 1.1163x; 1.1163x over previous
#include <cuda_runtime.h>
#include <math.h>

#define Bn 64
#define Tn 512
#define En 768
#define Cn 20
#define FULL 0xffffffffu

// scratch (no allocations allowed)
__device__ float g_em[Bn * Tn * Cn];   // emissions [B][T][C]
__device__ float g_norm[Bn];
__device__ float g_score[Bn];

__device__ __forceinline__ float neg_inf() { return __int_as_float(0xff800000); }

// ---------------------------------------------------------------------------
// Kernel 1: emissions = hidden @ fc_w^T + fc_b      (warp per row)
// grid = 444 (3 blocks/SM) -> 24 warps/SM so DRAM latency is hidden
// ---------------------------------------------------------------------------
extern "C" __global__ void __launch_bounds__(256)
k_emissions(const float* __restrict__ hidden,
            const float* __restrict__ fc_w,
            const float* __restrict__ fc_b) {
    extern __shared__ float sm[];          // Cn*En weights + Cn bias
    float* wsh = sm;
    float* bsh = sm + Cn * En;
    for (int i = threadIdx.x; i < Cn * En; i += blockDim.x) wsh[i] = fc_w[i];
    if (threadIdx.x < Cn) bsh[threadIdx.x] = fc_b[threadIdx.x];
    __syncthreads();

    const int lane  = threadIdx.x & 31;
    const int warp  = threadIdx.x >> 5;
    const int nwarp = (blockDim.x >> 5) * gridDim.x;
    const float4* w4 = (const float4*)wsh;

    for (int row = blockIdx.x * (blockDim.x >> 5) + warp; row < Bn * Tn; row += nwarp) {
        const float4* h4 = (const float4*)(hidden + (size_t)row * En);
        float acc[Cn];
#pragma unroll
        for (int c = 0; c < Cn; c++) acc[c] = (lane == 0) ? bsh[c] : 0.f;

#pragma unroll
        for (int k = 0; k < En / 128; k++) {           // 6 chunks of 128 floats
            float4 h = h4[lane + 32 * k];
#pragma unroll
            for (int c = 0; c < Cn; c++) {
                float4 w = w4[c * (En / 4) + lane + 32 * k];
                acc[c] = fmaf(h.x, w.x, fmaf(h.y, w.y, fmaf(h.z, w.z, fmaf(h.w, w.w, acc[c]))));
            }
        }
#pragma unroll
        for (int c = 0; c < Cn; c++) {
            acc[c] += __shfl_xor_sync(FULL, acc[c], 16);
            acc[c] += __shfl_xor_sync(FULL, acc[c], 8);
            acc[c] += __shfl_xor_sync(FULL, acc[c], 4);
            acc[c] += __shfl_xor_sync(FULL, acc[c], 2);
            acc[c] += __shfl_xor_sync(FULL, acc[c], 1);
        }
        if (lane == 0) {
            float4* o4 = (float4*)(g_em + (size_t)row * Cn);   // 80B stride: 16B aligned
            o4[0] = make_float4(acc[0],  acc[1],  acc[2],  acc[3]);
            o4[1] = make_float4(acc[4],  acc[5],  acc[6],  acc[7]);
            o4[2] = make_float4(acc[8],  acc[9],  acc[10], acc[11]);
            o4[3] = make_float4(acc[12], acc[13], acc[14], acc[15]);
            o4[4] = make_float4(acc[16], acc[17], acc[18], acc[19]);
        }
    }
}

// ---------------------------------------------------------------------------
// Kernel 2: blocks 0..63  -> numerator score + scaled forward (per batch)
//           blocks 64..127-> viterbi + backtrace, writes path into dout[1..]
// 128 threads stage emissions, warp 0 runs the recurrence
// ---------------------------------------------------------------------------
#define SM_EM    (Tn * Cn * 4)                 // 40960
#define SM_MSK   (Tn * 4)                      // 2048
#define SM_HIST  ((Tn - 1) * Cn)               // 10220
#define SM2_SIZE (SM_EM + SM_MSK + SM_HIST + 16)

extern "C" __global__ void __launch_bounds__(128)
k_crf(const int* __restrict__ amask,
      const int* __restrict__ labels,
      const float* __restrict__ start_t,
      const float* __restrict__ end_t,
      const float* __restrict__ trans,
      float* __restrict__ dout) {
    extern __shared__ char smraw[];
    float*         em_sh = (float*)smraw;
    int*           msk   = (int*)(smraw + SM_EM);
    unsigned char* hist  = (unsigned char*)(smraw + SM_EM + SM_MSK);

    const int tid  = threadIdx.x;
    const bool isfwd = (blockIdx.x < Bn);
    const int b = isfwd ? blockIdx.x : blockIdx.x - Bn;

    // stage emissions + mask for this batch (all 4 warps)
    {
        const float4* src = (const float4*)(g_em + (size_t)b * Tn * Cn);
        float4* dst = (float4*)em_sh;
#pragma unroll 4
        for (int i = tid; i < Tn * Cn / 4; i += 128) dst[i] = src[i];
        for (int i = tid; i < Tn; i += 128) msk[i] = amask[b * Tn + i];
    }
    __syncthreads();
    if (tid >= 32) return;                 // warps 1..3 retire

    const int lane = tid;
    const bool act = lane < Cn;
    const int jj = act ? lane : 0;          // clamped state index (avoid OOB)

    if (isfwd) {
        // ---- numerator: gold path score ----
        float ns = 0.f; int msum = 0;
        for (int t = lane; t < Tn; t += 32) {
            int tg = labels[b * Tn + t];
            msum += msk[t];
            if (t == 0) {
                ns += start_t[tg] + em_sh[tg];
            } else if (msk[t]) {
                int tp = labels[b * Tn + t - 1];
                ns += trans[tp * Cn + tg] + em_sh[t * Cn + tg];
            }
        }
        for (int o = 16; o; o >>= 1) {
            ns   += __shfl_xor_sync(FULL, ns, o);
            msum += __shfl_xor_sync(FULL, msum, o);
        }
        if (lane == 0) {
            int se = msum - 1;
            g_score[b] = ns + end_t[labels[b * Tn + se]];
        }

        // ---- denominator: scaled linear-domain forward ----
        float Mc[Cn];
#pragma unroll
        for (int i = 0; i < Cn; i++) Mc[i] = act ? expf(trans[i * Cn + jj]) : 0.f;

        float p = act ? expf(start_t[jj] + em_sh[jj]) : 0.f;
        float logZ = 0.f;

        for (int t = 1; t < Tn; t++) {
            float Ev = __expf(em_sh[t * Cn + jj]);    // off critical path
            float q0 = 0.f, q1 = 0.f, q2 = 0.f, q3 = 0.f;
#pragma unroll
            for (int i = 0; i < Cn; i += 4) {
                q0 = fmaf(__shfl_sync(FULL, p, i + 0), Mc[i + 0], q0);
                q1 = fmaf(__shfl_sync(FULL, p, i + 1), Mc[i + 1], q1);
                q2 = fmaf(__shfl_sync(FULL, p, i + 2), Mc[i + 2], q2);
                q3 = fmaf(__shfl_sync(FULL, p, i + 3), Mc[i + 3], q3);
            }
            float r = ((q0 + q1) + (q2 + q3)) * Ev;
            p = (msk[t] > 0) ? r : p;                 // lanes>=20 stay 0
            if ((t & 7) == 0) {                       // renormalize every 8 steps
                float s = p;
                for (int o = 16; o; o >>= 1) s += __shfl_xor_sync(FULL, s, o);
                p *= __fdividef(1.f, s);
                logZ += __logf(s);
            }
        }
        float fin = act ? p * __expf(end_t[jj]) : 0.f;
        for (int o = 16; o; o >>= 1) fin += __shfl_xor_sync(FULL, fin, o);
        if (lane == 0) g_norm[b] = logZ + __logf(fin);

    } else {
        // ---- viterbi: FMNMX max-tree on critical path, argmax off-path ----
        float Tc[Cn];
#pragma unroll
        for (int i = 0; i < Cn; i++) Tc[i] = act ? trans[i * Cn + jj] : 0.f;

        float a = act ? (start_t[jj] + em_sh[jj]) : neg_inf();

        for (int t = 1; t < Tn; t++) {
            float v[Cn];
#pragma unroll
            for (int i = 0; i < Cn; i++) v[i] = __shfl_sync(FULL, a, i) + Tc[i];

            // value max: pure FMNMX tree (lat 4, depth 5)
            float m0 = fmaxf(v[0],  v[1]);
            float m1 = fmaxf(v[2],  v[3]);
            float m2 = fmaxf(v[4],  v[5]);
            float m3 = fmaxf(v[6],  v[7]);
            float m4 = fmaxf(v[8],  v[9]);
            float m5 = fmaxf(v[10], v[11]);
            float m6 = fmaxf(v[12], v[13]);
            float m7 = fmaxf(v[14], v[15]);
            float m8 = fmaxf(v[16], v[17]);
            float m9 = fmaxf(v[18], v[19]);
            float n0 = fmaxf(m0, m1);
            float n1 = fmaxf(m2, m3);
            float n2 = fmaxf(m4, m5);
            float n3 = fmaxf(m6, m7);
            float n4 = fmaxf(m8, m9);
            float best = fmaxf(fmaxf(fmaxf(n0, n1), fmaxf(n2, n3)), n4);

            // recurrence continues immediately
            float na = best + em_sh[t * Cn + jj];

            // argmax (first max wins): exact equality mask, lowest set bit.
            // best is bitwise one of v[i]; v[i]==best at exactly the max entries.
            unsigned eqm = 0;
#pragma unroll
            for (int i = 0; i < Cn; i++) eqm |= (v[i] == best) ? (1u << i) : 0u;
            int bi = __ffs(eqm) - 1;
            if (act) hist[(t - 1) * Cn + lane] = (unsigned char)bi;

            a = (msk[t] > 0) ? na : a;    // garbage on inactive lanes, never read
        }

        // final argmax over states (first max on ties)
        float fv = act ? a + end_t[jj] : neg_inf();
        int fi = lane;
        for (int o = 16; o; o >>= 1) {
            float ov = __shfl_xor_sync(FULL, fv, o);
            int   oi = __shfl_xor_sync(FULL, fi, o);
            bool tk = (ov > fv) || (ov == fv && oi < fi);
            fv = tk ? ov : fv;
            fi = tk ? oi : fi;
        }
        __syncwarp();
        if (lane == 0) {
            int tg = fi;
            dout[1 + b * Tn + (Tn - 1)] = (float)(tg + 1);
            for (int t = Tn - 2; t >= 0; t--) {
                tg = hist[t * Cn + tg];
                dout[1 + b * Tn + t] = (float)(tg + 1);
            }
        }
    }
}

// ---------------------------------------------------------------------------
// Kernel 3: loss = mean(norm - score)   (one warp)
// ---------------------------------------------------------------------------
extern "C" __global__ void k_loss(float* __restrict__ dout) {
    int i = threadIdx.x;                          // 32 threads
    float v = g_norm[i] - g_score[i];
    v += g_norm[i + 32] - g_score[i + 32];
    for (int o = 16; o; o >>= 1) v += __shfl_xor_sync(FULL, v, o);
    if (i == 0) dout[0] = v / (float)Bn;
}

// ---------------------------------------------------------------------------
extern "C" void kernel_launch(void* const* d_in, const int* in_sizes, int n_in,
                              void* d_out, int out_size) {
    const float* hidden = (const float*)d_in[0];
    const int*   amask  = (const int*)d_in[1];
    const int*   labels = (const int*)d_in[2];
    const float* fc_w   = (const float*)d_in[3];
    const float* fc_b   = (const float*)d_in[4];
    const float* st     = (const float*)d_in[5];
    const float* en     = (const float*)d_in[6];
    const float* tr     = (const float*)d_in[7];
    float* dout = (float*)d_out;

    const int smem1 = (Cn * En + Cn) * 4;
    (void)cudaFuncSetAttribute((const void*)k_emissions,
                               cudaFuncAttributeMaxDynamicSharedMemorySize, smem1);
    (void)cudaFuncSetAttribute((const void*)k_crf,
                               cudaFuncAttributeMaxDynamicSharedMemorySize, SM2_SIZE);

    k_emissions<<<444, 256, smem1>>>(hidden, fc_w, fc_b);   // 3 blocks/SM
    k_crf<<<2 * Bn, 128, SM2_SIZE>>>(amask, labels, st, en, tr, dout);
    k_loss<<<1, 32>>>(dout);
}